// round 12
// baseline (speedup 1.0000x reference)
#include <cuda_runtime.h>
#include <cuda_fp16.h>
#include <stdint.h>
#include <math.h>

#define NB     16
#define NPTS   50000
#define HD     128
#define NL     5
#define NO     5
#define PDIM   8
#define TILE_M 384
#define TPB    131            // ceil(50000/384)
#define NJOBS  (NB * TPB)     // 2096
#define NCTA   152
#define NTHR   384            // 12 warps x m32 = 384 points/tile
#define LDW    136

// global scratch
__device__ float g_S [NB * NL * HD];
__device__ float g_bS[NB * NL * HD];
__device__ float g_zb[NB * NO];
__device__ __align__(16) __half g_Wb[4 * HD * LDW];      // hidden planes 0..3, alpha-folded
__device__ __align__(16) __half g_G [NB * 8 * LDW];      // per-batch folded Wf@Z^T (+alpha4)

// smem layout (bytes)
#define WBUF_BYTES (HD * LDW * 2)          // 34816
#define OFF_WALL 0                         // 4 planes = 139264
#define OFF_G    139264                    // 8*LDW fp16 = 2176
#define OFF_W0   141440                    // 3*128 f32
#define OFF_S    142976                    // 5*128 f32
#define OFF_BS   145536                    // 5*128 f32
#define OFF_ZB   148096                    // 8 f32
#define OFF_C    148128                    // 2 x 384*3 f32
#define CBUF     4608
#define SMEM_TOTAL 157344

// ---------------- helpers ----------------
__device__ __forceinline__ float tanh_fast(float x) {
    float t; asm("tanh.approx.f32 %0, %1;" : "=f"(t) : "f"(x)); return t;
}
__device__ __forceinline__ uint32_t pack_h2(float v0, float v1) {
    __half2 h = __floats2half2_rn(v0, v1);
    return *(uint32_t*)&h;
}
__device__ __forceinline__ uint32_t s2u(const void* p) {
    uint32_t a;
    asm("{ .reg .u64 t; cvta.to.shared.u64 t, %1; cvt.u32.u64 %0, t; }" : "=r"(a) : "l"(p));
    return a;
}
__device__ __forceinline__ void ldmatrix4(uint32_t& r0, uint32_t& r1, uint32_t& r2,
                                          uint32_t& r3, uint32_t addr) {
    asm volatile("ldmatrix.sync.aligned.m8n8.x4.shared.b16 {%0,%1,%2,%3}, [%4];"
                 : "=r"(r0), "=r"(r1), "=r"(r2), "=r"(r3) : "r"(addr));
}
__device__ __forceinline__ void ldmatrix2(uint32_t& r0, uint32_t& r1, uint32_t addr) {
    asm volatile("ldmatrix.sync.aligned.m8n8.x2.shared.b16 {%0,%1}, [%2];"
                 : "=r"(r0), "=r"(r1) : "r"(addr));
}
__device__ __forceinline__ void mma_f16(float& d0, float& d1, float& d2, float& d3,
                                        uint32_t a0, uint32_t a1, uint32_t a2, uint32_t a3,
                                        uint32_t b0, uint32_t b1) {
    asm volatile("mma.sync.aligned.m16n8k16.row.col.f32.f16.f16.f32 "
                 "{%0,%1,%2,%3}, {%4,%5,%6,%7}, {%8,%9}, {%0,%1,%2,%3};"
                 : "+f"(d0), "+f"(d1), "+f"(d2), "+f"(d3)
                 : "r"(a0), "r"(a1), "r"(a2), "r"(a3), "r"(b0), "r"(b1));
}
__device__ __forceinline__ void cp_async16(uint32_t saddr, const void* gptr) {
    asm volatile("cp.async.cg.shared.global [%0], [%1], 16;" :: "r"(saddr), "l"(gptr));
}
__device__ __forceinline__ void cp_commit() { asm volatile("cp.async.commit_group;" ::: "memory"); }
__device__ __forceinline__ void cp_wait0()  { asm volatile("cp.async.wait_group 0;"  ::: "memory"); }

// ---------------------------------------------------------------------------
// Prep: transpose hidden trunk weights, fold alpha -> fp16 planes (layers 0..3)
// ---------------------------------------------------------------------------
__global__ void prep_weights(const float* __restrict__ Wh,
                             const float* __restrict__ alpha)
{
    const int t     = blockIdx.x >> 3;
    const int slice = blockIdx.x & 7;
    const float* W = Wh + t * HD * HD;
    const float* al = alpha + t * HD;
    __half* dst = g_Wb + (size_t)t * HD * LDW;
    for (int idx = threadIdx.x; idx < 16 * HD; idx += blockDim.x) {
        int n = slice * 16 + (idx & 15);
        int k = idx >> 4;
        dst[n * LDW + k] = __float2half_rn(W[k * HD + n] * al[k]);
    }
}

// ---------------------------------------------------------------------------
// Branch MLP (exact tanhf): writes g_S, g_bS, g_zb, and folded G = a4*(Wf@Z^T)
// ---------------------------------------------------------------------------
__global__ void branch_kernel(const float* __restrict__ params,
                              const float* __restrict__ W0,
                              const float* __restrict__ b0,
                              const float* __restrict__ Wh,
                              const float* __restrict__ bh,
                              const float* __restrict__ alpha,
                              const float* __restrict__ Wf,
                              const float* __restrict__ bf,
                              const float* __restrict__ tb0,
                              const float* __restrict__ tbh,
                              const float* __restrict__ tbf,
                              const float* __restrict__ tWf,
                              const float* __restrict__ talpha)
{
    const int b = blockIdx.x;
    const int j = threadIdx.x;
    __shared__ float hs[HD];
    __shared__ float ps[PDIM];
    __shared__ float zsh[NO][HD];
    if (j < PDIM) ps[j] = params[b * PDIM + j];
    __syncthreads();

    float acc = b0[j];
#pragma unroll
    for (int k = 0; k < PDIM; ++k) acc = fmaf(ps[k], W0[k * HD + j], acc);
    float hv = alpha[j] * tanhf(acc);
    float S = hv;
    g_S [(b * NL + 0) * HD + j] = S;
    g_bS[(b * NL + 0) * HD + j] = tb0[j] * S;

    for (int i = 0; i < NL - 1; ++i) {
        hs[j] = hv;
        __syncthreads();
        float a2 = bh[i * HD + j];
#pragma unroll 8
        for (int k = 0; k < HD; ++k)
            a2 = fmaf(hs[k], Wh[(i * HD + k) * HD + j], a2);
        hv = alpha[(i + 1) * HD + j] * tanhf(a2);
        S += hv;
        g_S [(b * NL + i + 1) * HD + j] = S;
        g_bS[(b * NL + i + 1) * HD + j] = tbh[i * HD + j] * S;
        __syncthreads();
    }

    hs[j] = hv;
    __syncthreads();

    float zl[NO];
#pragma unroll
    for (int o = 0; o < NO; ++o) {
        float a2 = bf[o * HD + j];
#pragma unroll 8
        for (int k = 0; k < HD; ++k)
            a2 = fmaf(hs[k], Wf[k * (HD * NO) + o * HD + j], a2);
        zl[o] = a2;
        zsh[o][j] = a2;
    }
    float tb = tbf[j];
    __syncthreads();

#pragma unroll
    for (int o = 0; o < NO; ++o) {
        hs[j] = zl[o] * tb;
        __syncthreads();
#pragma unroll
        for (int s = 64; s > 0; s >>= 1) {
            if (j < s) hs[j] += hs[j + s];
            __syncthreads();
        }
        if (j == 0) g_zb[b * NO + o] = hs[0];
        __syncthreads();
    }

    {
        const float* wrow = tWf + j * HD;
        float a4 = talpha[4 * HD + j];
        __half* gdst = g_G + (size_t)b * 8 * LDW;
#pragma unroll
        for (int o = 0; o < NO; ++o) {
            float s = 0.f;
#pragma unroll 8
            for (int h = 0; h < HD; ++h) s = fmaf(wrow[h], zsh[o][h], s);
            gdst[o * LDW + j] = __float2half_rn(s * a4);
        }
#pragma unroll
        for (int o = NO; o < 8; ++o) gdst[o * LDW + j] = __ushort_as_half((unsigned short)0);
    }
}

// ---------------------------------------------------------------------------
// One hidden layer for an m32 warp tile, n16 pp-blocks (d = 16 regs).
// Reads A frags from aR, writes activated frags to aW (ping-pong).
// ---------------------------------------------------------------------------
__device__ __forceinline__ void layer_step(const uint32_t (&aR)[2][32],
                                           uint32_t (&aW)[2][32],
                                           uint32_t wb,
                                           const float* __restrict__ Sv,
                                           const float* __restrict__ Bv,
                                           int lane, int q)
{
    const int grp  = lane >> 3;
    const int nrow = (lane & 7) + ((grp >> 1) << 3);
    const int kcol = (grp & 1) << 3;
#pragma unroll
    for (int ppp = 0; ppp < 8; ++ppp) {
        float d[2][2][4];
#pragma unroll
        for (int m = 0; m < 2; ++m)
#pragma unroll
            for (int t = 0; t < 2; ++t)
#pragma unroll
                for (int r = 0; r < 4; ++r) d[m][t][r] = 0.f;

        const uint32_t base = wb + (uint32_t)(((nrow + ppp * 16) * LDW + kcol) * 2);
#pragma unroll
        for (int j = 0; j < 8; ++j) {
            uint32_t b0, b1, b2, b3;
            ldmatrix4(b0, b1, b2, b3, base + j * 32);
#pragma unroll
            for (int m = 0; m < 2; ++m) {
                mma_f16(d[m][0][0], d[m][0][1], d[m][0][2], d[m][0][3],
                        aR[m][4*j], aR[m][4*j+1], aR[m][4*j+2], aR[m][4*j+3], b0, b1);
                mma_f16(d[m][1][0], d[m][1][1], d[m][1][2], d[m][1][3],
                        aR[m][4*j], aR[m][4*j+1], aR[m][4*j+2], aR[m][4*j+3], b2, b3);
            }
        }

#pragma unroll
        for (int t = 0; t < 2; ++t) {
            int nt = 2 * ppp + t;
            int c = nt * 8 + q * 2;
            float2 ss = *(const float2*)&Sv[c];
            float2 bs = *(const float2*)&Bv[c];
            int base2 = 4 * ppp + 2 * t;
#pragma unroll
            for (int m = 0; m < 2; ++m) {
                float v00 = tanh_fast(fmaf(d[m][t][0], ss.x, bs.x));
                float v01 = tanh_fast(fmaf(d[m][t][1], ss.y, bs.y));
                float v10 = tanh_fast(fmaf(d[m][t][2], ss.x, bs.x));
                float v11 = tanh_fast(fmaf(d[m][t][3], ss.y, bs.y));
                aW[m][base2 + 0] = pack_h2(v00, v01);
                aW[m][base2 + 1] = pack_h2(v10, v11);
            }
        }
    }
}

// ---------------------------------------------------------------------------
// Trunk: persistent CTAs. 384 threads = 12 warps x m32 = 384 points/tile.
// ---------------------------------------------------------------------------
__global__ void __launch_bounds__(NTHR, 1)
trunk_kernel(const float* __restrict__ coords,
             const float* __restrict__ tW0,
             float* __restrict__ out)
{
    extern __shared__ char sm[];
    const uint32_t sbase = s2u(sm);
    const int tid  = threadIdx.x;
    const int lane = tid & 31;
    const int warp = tid >> 5;
    const int q    = lane & 3;
    const int g4   = lane >> 2;
    const int cta  = blockIdx.x;

    const int jstart = (int)(((long)cta * NJOBS) / NCTA);
    const int jend   = (int)(((long)(cta + 1) * NJOBS) / NCTA);

    float* sW0 = (float*)(sm + OFF_W0);
    float* sS  = (float*)(sm + OFF_S);
    float* sBS = (float*)(sm + OFF_BS);
    float* sZB = (float*)(sm + OFF_ZB);

    // ---- prologue: 4 hidden planes + first coords ----
    {
        const char* src = (const char*)g_Wb;
#pragma unroll 4
        for (int i = tid; i < 4 * WBUF_BYTES / 16; i += NTHR)
            cp_async16(sbase + OFF_WALL + i * 16, src + i * 16);
        int jb = jstart / TPB, jt = jstart - jb * TPB;
        int nn0 = jt * TILE_M;
        int nnv = min(TILE_M, NPTS - nn0);
        const char* csrc = (const char*)(coords + ((size_t)jb * NPTS + nn0) * 3);
        for (int i = tid; i < nnv * 3 / 4; i += NTHR)
            cp_async16(sbase + OFF_C + i * 16, csrc + i * 16);
        cp_commit();
    }
    for (int i = tid; i < 3 * HD; i += NTHR) sW0[i] = tW0[i];
    cp_wait0();

    const int w32 = warp * 32;
    int cur_b = -1;
    int p = 0;

    for (int job = jstart; job < jend; ++job) {
        const int b    = job / TPB;
        const int tile = job - b * TPB;
        const int n0   = tile * TILE_M;
        const int nv   = min(TILE_M, NPTS - n0);

        // prefetch next tile's coords
        if (job + 1 < jend) {
            int jb = (job + 1) / TPB, jt = (job + 1) - jb * TPB;
            int nn0 = jt * TILE_M;
            int nnv = min(TILE_M, NPTS - nn0);
            const char* csrc = (const char*)(coords + ((size_t)jb * NPTS + nn0) * 3);
            uint32_t dst = sbase + OFF_C + (uint32_t)((p ^ 1) * CBUF);
            for (int i = tid; i < nnv * 3 / 4; i += NTHR)
                cp_async16(dst + i * 16, csrc + i * 16);
            cp_commit();
        }

        if (b != cur_b) {
            for (int i = tid; i < NL * HD; i += NTHR) {
                sS[i]  = g_S [b * NL * HD + i];
                sBS[i] = g_bS[b * NL * HD + i];
            }
            {
                const uint32_t* gsrc = (const uint32_t*)(g_G + (size_t)b * 8 * LDW);
                uint32_t* gdst = (uint32_t*)(sm + OFF_G);
                for (int i = tid; i < 8 * LDW / 2; i += NTHR) gdst[i] = gsrc[i];
            }
            if (tid < NO) sZB[tid] = g_zb[b * NO + tid];
            cur_b = b;
            __syncthreads();
        }

        const float* sC = (const float*)(sm + OFF_C + p * CBUF);
        uint32_t abuf[2][2][32];   // [pingpong][m][frag]

        // ---- entry layer -> abuf[0] ----
        {
            float cc[4][3];
#pragma unroll
            for (int h = 0; h < 4; ++h) {
                int r = w32 + g4 + 8 * h;
                cc[h][0] = sC[r * 3 + 0];
                cc[h][1] = sC[r * 3 + 1];
                cc[h][2] = sC[r * 3 + 2];
            }
#pragma unroll
            for (int nt = 0; nt < 16; ++nt) {
                int c = nt * 8 + q * 2;
                float2 w0 = *(const float2*)&sW0[c];
                float2 w1 = *(const float2*)&sW0[HD + c];
                float2 w2 = *(const float2*)&sW0[2 * HD + c];
                float2 ss = *(const float2*)&sS[c];
                float2 bs = *(const float2*)&sBS[c];
                int base = 4 * (nt >> 1) + (nt & 1) * 2;
#pragma unroll
                for (int h = 0; h < 4; ++h) {
                    float v0 = cc[h][0] * w0.x + cc[h][1] * w1.x + cc[h][2] * w2.x;
                    float v1 = cc[h][0] * w0.y + cc[h][1] * w1.y + cc[h][2] * w2.y;
                    v0 = tanh_fast(fmaf(v0, ss.x, bs.x));
                    v1 = tanh_fast(fmaf(v1, ss.y, bs.y));
                    abuf[0][h >> 1][base + (h & 1)] = pack_h2(v0, v1);
                }
            }
        }

        // ---- hidden layers 0..3, ping-pong (parity ends at 0) ----
#pragma unroll 1
        for (int gg = 0; gg < 2; ++gg) {
            const int g0 = 2 * gg;
            layer_step(abuf[0], abuf[1],
                       sbase + OFF_WALL + (uint32_t)(g0 * WBUF_BYTES),
                       sS + (g0 + 1) * HD, sBS + (g0 + 1) * HD, lane, q);
            layer_step(abuf[1], abuf[0],
                       sbase + OFF_WALL + (uint32_t)((g0 + 1) * WBUF_BYTES),
                       sS + (g0 + 2) * HD, sBS + (g0 + 2) * HD, lane, q);
        }

        // ---- final: thin n=8 GEMM against G ----
        {
            float d[2][4];
#pragma unroll
            for (int m = 0; m < 2; ++m)
#pragma unroll
                for (int r = 0; r < 4; ++r) d[m][r] = 0.f;

            const uint32_t gaddr = sbase + OFF_G +
                (uint32_t)(((lane & 7) * LDW + ((lane >> 3) & 1) * 8) * 2);
#pragma unroll
            for (int j = 0; j < 8; ++j) {
                uint32_t b0, b1;
                ldmatrix2(b0, b1, gaddr + j * 32);
#pragma unroll
                for (int m = 0; m < 2; ++m)
                    mma_f16(d[m][0], d[m][1], d[m][2], d[m][3],
                            abuf[0][m][4*j], abuf[0][m][4*j+1],
                            abuf[0][m][4*j+2], abuf[0][m][4*j+3], b0, b1);
            }

            const int o0 = 2 * q, o1 = 2 * q + 1;
            const float zb0 = (o0 < NO) ? sZB[o0] : 0.f;
            const float zb1 = (o1 < NO) ? sZB[o1] : 0.f;
#pragma unroll
            for (int m = 0; m < 2; ++m)
#pragma unroll
                for (int half = 0; half < 2; ++half) {
                    int r = w32 + 16 * m + 8 * half + g4;
                    if (r < nv) {
                        float* op = out + ((size_t)b * NPTS + n0 + r) * NO;
                        if (o0 < NO) op[o0] = d[m][2 * half + 0] + zb0;
                        if (o1 < NO) op[o1] = d[m][2 * half + 1] + zb1;
                    }
                }
        }

        cp_wait0();
        __syncthreads();
        p ^= 1;
    }
}

// ---------------------------------------------------------------------------
// Launch
// ---------------------------------------------------------------------------
extern "C" void kernel_launch(void* const* d_in, const int* in_sizes, int n_in,
                              void* d_out, int out_size)
{
    const float* coords = (const float*)d_in[0];
    const float* params = (const float*)d_in[1];
    const float* bW0    = (const float*)d_in[2];
    const float* bb0    = (const float*)d_in[3];
    const float* bWh    = (const float*)d_in[4];
    const float* bbh    = (const float*)d_in[5];
    const float* balpha = (const float*)d_in[6];
    const float* bWf    = (const float*)d_in[7];
    const float* bbf    = (const float*)d_in[8];
    const float* tW0    = (const float*)d_in[9];
    const float* tb0    = (const float*)d_in[10];
    const float* tWh    = (const float*)d_in[11];
    const float* tbh    = (const float*)d_in[12];
    const float* talpha = (const float*)d_in[13];
    const float* tWf    = (const float*)d_in[14];
    const float* tbf    = (const float*)d_in[15];
    float* out = (float*)d_out;

    cudaFuncSetAttribute(trunk_kernel,
                         cudaFuncAttributeMaxDynamicSharedMemorySize, SMEM_TOTAL);

    prep_weights<<<32, 256>>>(tWh, talpha);
    branch_kernel<<<NB, HD>>>(params, bW0, bb0, bWh, bbh, balpha, bWf, bbf,
                              tb0, tbh, tbf, tWf, talpha);

    trunk_kernel<<<NCTA, NTHR, SMEM_TOTAL>>>(coords, tW0, out);
}

// round 13
// speedup vs baseline: 1.1012x; 1.1012x over previous
#include <cuda_runtime.h>
#include <cuda_fp16.h>
#include <stdint.h>
#include <math.h>

#define NB     16
#define NPTS   50000
#define HD     128
#define NL     5
#define NO     5
#define PDIM   8
#define TILE_M 256
#define TPB    196            // ceil(50000/256)
#define NJOBS  (NB * TPB)     // 3136
#define NCTA   152
#define NTHR   256            // 8 warps x m32 = 256 points/tile
#define LDW    136

// global scratch
__device__ float g_S [NB * NL * HD];
__device__ float g_bS[NB * NL * HD];
__device__ float g_zb[NB * NO];
__device__ __align__(16) __half g_Wb[4 * HD * LDW];      // hidden planes 0..3, alpha-folded
__device__ __align__(16) __half g_G [NB * 8 * LDW];      // per-batch folded Wf@Z^T (+alpha4)

// smem layout (bytes)
#define WBUF_BYTES (HD * LDW * 2)          // 34816
#define OFF_WALL 0                         // 4 planes = 139264
#define OFF_G    139264                    // 8*LDW fp16 = 2176
#define OFF_W0   141440                    // 3*128 f32 = 1536
#define OFF_SB   142976                    // 5 layers x 64 float4 = 5120
#define OFF_ZB   148096                    // 8 f32
#define OFF_C    148128                    // 2 x 256*3 f32
#define CBUF     3072
#define SMEM_TOTAL 154272

// ---------------- helpers ----------------
__device__ __forceinline__ float tanh_fast(float x) {
    float t; asm("tanh.approx.f32 %0, %1;" : "=f"(t) : "f"(x)); return t;
}
__device__ __forceinline__ uint32_t pack_h2(float v0, float v1) {
    __half2 h = __floats2half2_rn(v0, v1);
    return *(uint32_t*)&h;
}
__device__ __forceinline__ uint32_t s2u(const void* p) {
    uint32_t a;
    asm("{ .reg .u64 t; cvta.to.shared.u64 t, %1; cvt.u32.u64 %0, t; }" : "=r"(a) : "l"(p));
    return a;
}
__device__ __forceinline__ void ldmatrix4(uint32_t& r0, uint32_t& r1, uint32_t& r2,
                                          uint32_t& r3, uint32_t addr) {
    asm volatile("ldmatrix.sync.aligned.m8n8.x4.shared.b16 {%0,%1,%2,%3}, [%4];"
                 : "=r"(r0), "=r"(r1), "=r"(r2), "=r"(r3) : "r"(addr));
}
__device__ __forceinline__ void ldmatrix2(uint32_t& r0, uint32_t& r1, uint32_t addr) {
    asm volatile("ldmatrix.sync.aligned.m8n8.x2.shared.b16 {%0,%1}, [%2];"
                 : "=r"(r0), "=r"(r1) : "r"(addr));
}
__device__ __forceinline__ void mma_f16(float& d0, float& d1, float& d2, float& d3,
                                        uint32_t a0, uint32_t a1, uint32_t a2, uint32_t a3,
                                        uint32_t b0, uint32_t b1) {
    asm volatile("mma.sync.aligned.m16n8k16.row.col.f32.f16.f16.f32 "
                 "{%0,%1,%2,%3}, {%4,%5,%6,%7}, {%8,%9}, {%0,%1,%2,%3};"
                 : "+f"(d0), "+f"(d1), "+f"(d2), "+f"(d3)
                 : "r"(a0), "r"(a1), "r"(a2), "r"(a3), "r"(b0), "r"(b1));
}
__device__ __forceinline__ void cp_async16(uint32_t saddr, const void* gptr) {
    asm volatile("cp.async.cg.shared.global [%0], [%1], 16;" :: "r"(saddr), "l"(gptr));
}
__device__ __forceinline__ void cp_commit() { asm volatile("cp.async.commit_group;" ::: "memory"); }
__device__ __forceinline__ void cp_wait0()  { asm volatile("cp.async.wait_group 0;"  ::: "memory"); }

// ---------------------------------------------------------------------------
// Fused setup: blocks 0..31 prep weights; blocks 32..47 run the branch MLP.
// 128 threads per block.
// ---------------------------------------------------------------------------
__global__ void setup_kernel(const float* __restrict__ params,
                             const float* __restrict__ W0,
                             const float* __restrict__ b0,
                             const float* __restrict__ Wh,
                             const float* __restrict__ bh,
                             const float* __restrict__ alpha,
                             const float* __restrict__ Wf,
                             const float* __restrict__ bf,
                             const float* __restrict__ tW0,
                             const float* __restrict__ tb0,
                             const float* __restrict__ tWh,
                             const float* __restrict__ tbh,
                             const float* __restrict__ talpha,
                             const float* __restrict__ tWf,
                             const float* __restrict__ tbf)
{
    if (blockIdx.x < 32) {
        // ---- weight prep: transpose + alpha-fold -> fp16 planes (layers 0..3)
        const int t     = blockIdx.x >> 3;
        const int slice = blockIdx.x & 7;
        const float* W = tWh + t * HD * HD;
        const float* al = talpha + t * HD;
        __half* dst = g_Wb + (size_t)t * HD * LDW;
        for (int idx = threadIdx.x; idx < 16 * HD; idx += blockDim.x) {
            int n = slice * 16 + (idx & 15);
            int k = idx >> 4;
            dst[n * LDW + k] = __float2half_rn(W[k * HD + n] * al[k]);
        }
        return;
    }

    // ---- branch MLP (exact tanhf): writes g_S, g_bS, g_zb, folded G ----
    const int b = blockIdx.x - 32;
    const int j = threadIdx.x;
    __shared__ float hs[HD];
    __shared__ float ps[PDIM];
    __shared__ float zsh[NO][HD];
    if (j < PDIM) ps[j] = params[b * PDIM + j];
    __syncthreads();

    float acc = b0[j];
#pragma unroll
    for (int k = 0; k < PDIM; ++k) acc = fmaf(ps[k], W0[k * HD + j], acc);
    float hv = alpha[j] * tanhf(acc);
    float S = hv;
    g_S [(b * NL + 0) * HD + j] = S;
    g_bS[(b * NL + 0) * HD + j] = tb0[j] * S;

    for (int i = 0; i < NL - 1; ++i) {
        hs[j] = hv;
        __syncthreads();
        float a2 = bh[i * HD + j];
#pragma unroll 8
        for (int k = 0; k < HD; ++k)
            a2 = fmaf(hs[k], Wh[(i * HD + k) * HD + j], a2);
        hv = alpha[(i + 1) * HD + j] * tanhf(a2);
        S += hv;
        g_S [(b * NL + i + 1) * HD + j] = S;
        g_bS[(b * NL + i + 1) * HD + j] = tbh[i * HD + j] * S;
        __syncthreads();
    }

    hs[j] = hv;
    __syncthreads();

    float zl[NO];
#pragma unroll
    for (int o = 0; o < NO; ++o) {
        float a2 = bf[o * HD + j];
#pragma unroll 8
        for (int k = 0; k < HD; ++k)
            a2 = fmaf(hs[k], Wf[k * (HD * NO) + o * HD + j], a2);
        zl[o] = a2;
        zsh[o][j] = a2;
    }
    float tb = tbf[j];
    __syncthreads();

#pragma unroll
    for (int o = 0; o < NO; ++o) {
        hs[j] = zl[o] * tb;
        __syncthreads();
#pragma unroll
        for (int s = 64; s > 0; s >>= 1) {
            if (j < s) hs[j] += hs[j + s];
            __syncthreads();
        }
        if (j == 0) g_zb[b * NO + o] = hs[0];
        __syncthreads();
    }

    {
        const float* wrow = tWf + j * HD;
        float a4 = talpha[4 * HD + j];
        __half* gdst = g_G + (size_t)b * 8 * LDW;
#pragma unroll
        for (int o = 0; o < NO; ++o) {
            float s = 0.f;
#pragma unroll 8
            for (int h = 0; h < HD; ++h) s = fmaf(wrow[h], zsh[o][h], s);
            gdst[o * LDW + j] = __float2half_rn(s * a4);
        }
#pragma unroll
        for (int o = NO; o < 8; ++o) gdst[o * LDW + j] = __ushort_as_half((unsigned short)0);
    }
}

// ---------------------------------------------------------------------------
// One pp-block (32 output cols) for an m32 warp tile: 2 m16 blocks share B.
// ---------------------------------------------------------------------------
__device__ __forceinline__ void mma_block32(float (&d)[2][4][4],
                                            const uint32_t (&ah)[2][32],
                                            uint32_t wbase, int pp, int lane)
{
    const int grp  = lane >> 3;
    const int nrow = (lane & 7) + ((grp >> 1) << 3);
    const int kcol = (grp & 1) << 3;
    const uint32_t base0 = wbase + (uint32_t)(((nrow + (2 * pp)     * 16) * LDW + kcol) * 2);
    const uint32_t base1 = wbase + (uint32_t)(((nrow + (2 * pp + 1) * 16) * LDW + kcol) * 2);
#pragma unroll
    for (int j = 0; j < 8; ++j) {
        uint32_t b0, b1, b2, b3, c0, c1, c2, c3;
        ldmatrix4(b0, b1, b2, b3, base0 + j * 32);
        ldmatrix4(c0, c1, c2, c3, base1 + j * 32);
#pragma unroll
        for (int m = 0; m < 2; ++m) {
            mma_f16(d[m][0][0], d[m][0][1], d[m][0][2], d[m][0][3],
                    ah[m][4*j], ah[m][4*j+1], ah[m][4*j+2], ah[m][4*j+3], b0, b1);
            mma_f16(d[m][1][0], d[m][1][1], d[m][1][2], d[m][1][3],
                    ah[m][4*j], ah[m][4*j+1], ah[m][4*j+2], ah[m][4*j+3], b2, b3);
            mma_f16(d[m][2][0], d[m][2][1], d[m][2][2], d[m][2][3],
                    ah[m][4*j], ah[m][4*j+1], ah[m][4*j+2], ah[m][4*j+3], c0, c1);
            mma_f16(d[m][3][0], d[m][3][1], d[m][3][2], d[m][3][3],
                    ah[m][4*j], ah[m][4*j+1], ah[m][4*j+2], ah[m][4*j+3], c2, c3);
        }
    }
}

// ---------------------------------------------------------------------------
// Trunk: persistent CTAs. 256 threads = 8 warps x m32 = 256 points/tile.
// ---------------------------------------------------------------------------
__global__ void __launch_bounds__(NTHR, 1)
trunk_kernel(const float* __restrict__ coords,
             const float* __restrict__ tW0,
             float* __restrict__ out)
{
    extern __shared__ char sm[];
    const uint32_t sbase = s2u(sm);
    const int tid  = threadIdx.x;
    const int lane = tid & 31;
    const int warp = tid >> 5;
    const int q    = lane & 3;
    const int g4   = lane >> 2;
    const int cta  = blockIdx.x;

    const int jstart = (int)(((long)cta * NJOBS) / NCTA);
    const int jend   = (int)(((long)(cta + 1) * NJOBS) / NCTA);

    float* sW0 = (float*)(sm + OFF_W0);
    float4* sSB = (float4*)(sm + OFF_SB);   // [layer][pair] = {S[c],S[c+1],bS[c],bS[c+1]}
    float* sZB = (float*)(sm + OFF_ZB);

    // ---- prologue: 4 hidden planes + first coords ----
    {
        const char* src = (const char*)g_Wb;
#pragma unroll 4
        for (int i = tid; i < 4 * WBUF_BYTES / 16; i += NTHR)
            cp_async16(sbase + OFF_WALL + i * 16, src + i * 16);
        int jb = jstart / TPB, jt = jstart - jb * TPB;
        int nn0 = jt * TILE_M;
        int nnv = min(TILE_M, NPTS - nn0);
        const char* csrc = (const char*)(coords + ((size_t)jb * NPTS + nn0) * 3);
        for (int i = tid; i < nnv * 3 / 4; i += NTHR)
            cp_async16(sbase + OFF_C + i * 16, csrc + i * 16);
        cp_commit();
    }
    for (int i = tid; i < 3 * HD; i += NTHR) sW0[i] = tW0[i];
    cp_wait0();

    const int w32 = warp * 32;
    int cur_b = -1;
    int p = 0;

    for (int job = jstart; job < jend; ++job) {
        const int b    = job / TPB;
        const int tile = job - b * TPB;
        const int n0   = tile * TILE_M;
        const int nv   = min(TILE_M, NPTS - n0);

        // prefetch next tile's coords
        if (job + 1 < jend) {
            int jb = (job + 1) / TPB, jt = (job + 1) - jb * TPB;
            int nn0 = jt * TILE_M;
            int nnv = min(TILE_M, NPTS - nn0);
            const char* csrc = (const char*)(coords + ((size_t)jb * NPTS + nn0) * 3);
            uint32_t dst = sbase + OFF_C + (uint32_t)((p ^ 1) * CBUF);
            for (int i = tid; i < nnv * 3 / 4; i += NTHR)
                cp_async16(dst + i * 16, csrc + i * 16);
            cp_commit();
        }

        if (b != cur_b) {
            // build interleaved {S,S,bS,bS} quads per layer
            for (int i = tid; i < NL * 64; i += NTHR) {
                int l = i >> 6;
                int c = (i & 63) * 2;
                const float* Sg = g_S  + (b * NL + l) * HD;
                const float* Bg = g_bS + (b * NL + l) * HD;
                sSB[i] = make_float4(Sg[c], Sg[c + 1], Bg[c], Bg[c + 1]);
            }
            {
                const uint32_t* gsrc = (const uint32_t*)(g_G + (size_t)b * 8 * LDW);
                uint32_t* gdst = (uint32_t*)(sm + OFF_G);
                for (int i = tid; i < 8 * LDW / 2; i += NTHR) gdst[i] = gsrc[i];
            }
            if (tid < NO) sZB[tid] = g_zb[b * NO + tid];
            cur_b = b;
            __syncthreads();
        }

        const float* sC = (const float*)(sm + OFF_C + p * CBUF);
        uint32_t ah[2][32];

        // ---- entry layer ----
        {
            float cc[4][3];
#pragma unroll
            for (int h = 0; h < 4; ++h) {
                int r = w32 + g4 + 8 * h;
                cc[h][0] = sC[r * 3 + 0];
                cc[h][1] = sC[r * 3 + 1];
                cc[h][2] = sC[r * 3 + 2];
            }
#pragma unroll
            for (int nt = 0; nt < 16; ++nt) {
                int c = nt * 8 + q * 2;
                float2 w0 = *(const float2*)&sW0[c];
                float2 w1 = *(const float2*)&sW0[HD + c];
                float2 w2 = *(const float2*)&sW0[2 * HD + c];
                float4 sb = sSB[nt * 4 + q];            // layer 0
                int base = 4 * (nt >> 1) + (nt & 1) * 2;
#pragma unroll
                for (int h = 0; h < 4; ++h) {
                    float v0 = cc[h][0] * w0.x + cc[h][1] * w1.x + cc[h][2] * w2.x;
                    float v1 = cc[h][0] * w0.y + cc[h][1] * w1.y + cc[h][2] * w2.y;
                    v0 = tanh_fast(fmaf(v0, sb.x, sb.z));
                    v1 = tanh_fast(fmaf(v1, sb.y, sb.w));
                    ah[h >> 1][base + (h & 1)] = pack_h2(v0, v1);
                }
            }
        }

        // ---- hidden layers 0..3 ----
#pragma unroll 1
        for (int g = 0; g < 4; ++g) {
            const uint32_t wb = sbase + OFF_WALL + (uint32_t)(g * WBUF_BYTES);
            const float4* SBl = sSB + (g + 1) * 64;
            uint32_t ahn[2][32];
#pragma unroll
            for (int pp = 0; pp < 4; ++pp) {
                float d[2][4][4];
#pragma unroll
                for (int m = 0; m < 2; ++m)
#pragma unroll
                    for (int t = 0; t < 4; ++t)
#pragma unroll
                        for (int r = 0; r < 4; ++r) d[m][t][r] = 0.f;

                mma_block32(d, ah, wb, pp, lane);

#pragma unroll
                for (int t = 0; t < 4; ++t) {
                    int nt = 4 * pp + t;
                    float4 sb = SBl[nt * 4 + q];
                    int base = 8 * pp + 4 * (t >> 1) + 2 * (t & 1);
#pragma unroll
                    for (int m = 0; m < 2; ++m) {
                        float v00 = tanh_fast(fmaf(d[m][t][0], sb.x, sb.z));
                        float v01 = tanh_fast(fmaf(d[m][t][1], sb.y, sb.w));
                        float v10 = tanh_fast(fmaf(d[m][t][2], sb.x, sb.z));
                        float v11 = tanh_fast(fmaf(d[m][t][3], sb.y, sb.w));
                        ahn[m][base + 0] = pack_h2(v00, v01);
                        ahn[m][base + 1] = pack_h2(v10, v11);
                    }
                }
            }
#pragma unroll
            for (int m = 0; m < 2; ++m)
#pragma unroll
                for (int i = 0; i < 32; ++i) ah[m][i] = ahn[m][i];
        }

        // ---- final: thin n=8 GEMM against G ----
        {
            float d[2][4];
#pragma unroll
            for (int m = 0; m < 2; ++m)
#pragma unroll
                for (int r = 0; r < 4; ++r) d[m][r] = 0.f;

            const uint32_t gaddr = sbase + OFF_G +
                (uint32_t)(((lane & 7) * LDW + ((lane >> 3) & 1) * 8) * 2);
#pragma unroll
            for (int j = 0; j < 8; ++j) {
                uint32_t b0, b1;
                ldmatrix2(b0, b1, gaddr + j * 32);
#pragma unroll
                for (int m = 0; m < 2; ++m)
                    mma_f16(d[m][0], d[m][1], d[m][2], d[m][3],
                            ah[m][4*j], ah[m][4*j+1], ah[m][4*j+2], ah[m][4*j+3], b0, b1);
            }

            const int o0 = 2 * q, o1 = 2 * q + 1;
            const float zb0 = (o0 < NO) ? sZB[o0] : 0.f;
            const float zb1 = (o1 < NO) ? sZB[o1] : 0.f;
#pragma unroll
            for (int m = 0; m < 2; ++m)
#pragma unroll
                for (int half = 0; half < 2; ++half) {
                    int r = w32 + 16 * m + 8 * half + g4;
                    if (r < nv) {
                        float* op = out + ((size_t)b * NPTS + n0 + r) * NO;
                        if (o0 < NO) op[o0] = d[m][2 * half + 0] + zb0;
                        if (o1 < NO) op[o1] = d[m][2 * half + 1] + zb1;
                    }
                }
        }

        cp_wait0();
        __syncthreads();
        p ^= 1;
    }
}

// ---------------------------------------------------------------------------
// Launch
// ---------------------------------------------------------------------------
extern "C" void kernel_launch(void* const* d_in, const int* in_sizes, int n_in,
                              void* d_out, int out_size)
{
    const float* coords = (const float*)d_in[0];
    const float* params = (const float*)d_in[1];
    const float* bW0    = (const float*)d_in[2];
    const float* bb0    = (const float*)d_in[3];
    const float* bWh    = (const float*)d_in[4];
    const float* bbh    = (const float*)d_in[5];
    const float* balpha = (const float*)d_in[6];
    const float* bWf    = (const float*)d_in[7];
    const float* bbf    = (const float*)d_in[8];
    const float* tW0    = (const float*)d_in[9];
    const float* tb0    = (const float*)d_in[10];
    const float* tWh    = (const float*)d_in[11];
    const float* tbh    = (const float*)d_in[12];
    const float* talpha = (const float*)d_in[13];
    const float* tWf    = (const float*)d_in[14];
    const float* tbf    = (const float*)d_in[15];
    float* out = (float*)d_out;

    cudaFuncSetAttribute(trunk_kernel,
                         cudaFuncAttributeMaxDynamicSharedMemorySize, SMEM_TOTAL);

    setup_kernel<<<48, 128>>>(params, bW0, bb0, bWh, bbh, balpha, bWf, bbf,
                              tW0, tb0, tWh, tbh, talpha, tWf, tbf);

    trunk_kernel<<<NCTA, NTHR, SMEM_TOTAL>>>(coords, tW0, out);
}